// round 13
// baseline (speedup 1.0000x reference)
#include <cuda_runtime.h>

#define BB 64
#define NQv 1024
#define LLv 128
#define EEv 8192

// ---------------- scratch (static device globals; no allocations) ----------
__device__ float g_h[BB * NQv * LLv];      // node states (exact fp32)
__device__ float g_A[BB * NQv * LLv];      // h @ W1a^T + b1   (round 1)
__device__ float g_Bv[BB * NQv * LLv];     // h @ W1b^T        (round 1)
__device__ float g_w1abT[LLv * LLv];       // (w1a[0]+w1b[0])^T  [k][c]
__device__ float g_w1c[2][LLv];            // e_w1[:, :, 256]
__device__ float g_eb1c[LLv];              // e_b1[0] copy (base bias)
// fragment-packed tf32 weights: chunk16 = 2048 floats (16 k x 128 cols),
// float2 fragment layout: j = (((chunk*2+ks)*16+cg)*32 + g*4+tig)*2 + p
__device__ __align__(16) float g_pw1a[16384], g_pw1b[16384];
__device__ __align__(16) float g_pew2[2][16384];
__device__ __align__(16) float g_pnw1[2][32768];
__device__ __align__(16) float g_pnw2[2][16384];
__device__ int   g_src[EEv];
__device__ int   g_tgt[EEv];
__device__ int   g_rowptr[NQv + 1];
__device__ int   g_csr_tgt[EEv];
__device__ float g_csr_ea[EEv];
__device__ int   g_is64;

// ---------------- tf32 / mma / cp.async helpers ------------------------------
__device__ __forceinline__ float f2tf32f(float x) {
    unsigned r;
    asm("cvt.rna.tf32.f32 %0, %1;" : "=r"(r) : "f"(x));
    return __uint_as_float(r);
}
__device__ __forceinline__ void mma_tf32(float (&c)[4],
    unsigned a0, unsigned a1, unsigned a2, unsigned a3,
    unsigned b0, unsigned b1)
{
    asm volatile(
        "mma.sync.aligned.m16n8k8.row.col.f32.tf32.tf32.f32 "
        "{%0,%1,%2,%3}, {%4,%5,%6,%7}, {%8,%9}, {%0,%1,%2,%3};"
        : "+f"(c[0]), "+f"(c[1]), "+f"(c[2]), "+f"(c[3])
        : "r"(a0), "r"(a1), "r"(a2), "r"(a3), "r"(b0), "r"(b1));
}
__device__ __forceinline__ void zacc4(float (&c)[4][4]) {
#pragma unroll
    for (int b = 0; b < 4; b++)
#pragma unroll
        for (int i = 0; i < 4; i++) c[b][i] = 0.f;
}
__device__ __forceinline__ void zacc2(float (&c)[2][4][4]) {
#pragma unroll
    for (int a = 0; a < 2; a++)
#pragma unroll
        for (int b = 0; b < 4; b++)
#pragma unroll
            for (int i = 0; i < 4; i++) c[a][b][i] = 0.f;
}
__device__ __forceinline__ void cpa16(float* dst, const float* src) {
    unsigned d = (unsigned)__cvta_generic_to_shared(dst);
    asm volatile("cp.async.cg.shared.global [%0], [%1], 16;" :: "r"(d), "l"(src));
}
__device__ __forceinline__ void cpa_commit() {
    asm volatile("cp.async.commit_group;" ::: "memory");
}
template<int N> __device__ __forceinline__ void cpa_wait() {
    asm volatile("cp.async.wait_group %0;" :: "n"(N) : "memory");
}
// 16-k weight chunk = 2048 floats
template<int NT>
__device__ __forceinline__ void pf_chunk(float* buf, const float* Wp, int t) {
#pragma unroll
    for (int i = 0; i < 2048 / (4 * NT); i++)
        cpa16(buf + (i * NT + t) * 4, Wp + (i * NT + t) * 4);
    cpa_commit();
}

// 16-row warp tile: C[16][32] += Xs(16 rows) @ W^T cols [wn*32,+32), one chunk16
template<int XST>
__device__ __forceinline__ void compute_chunk16(
    float (&c)[4][4], const float* Xs, int kkbase,
    const float* buf, int lane, int wn)
{
    int g = lane >> 2, tig = lane & 3;
    const float2* bf = (const float2*)buf;
#pragma unroll
    for (int ks = 0; ks < 2; ks++) {
        const float* xr  = Xs + g * XST + kkbase + ks * 8;
        const float* xr8 = xr + 8 * XST;
        unsigned a0 = __float_as_uint(xr[tig]);
        unsigned a1 = __float_as_uint(xr8[tig]);
        unsigned a2 = __float_as_uint(xr[tig + 4]);
        unsigned a3 = __float_as_uint(xr8[tig + 4]);
#pragma unroll
        for (int nf = 0; nf < 4; nf++) {
            float2 bb = bf[(ks * 16 + wn * 4 + nf) * 32 + g * 4 + tig];
            mma_tf32(c[nf], a0, a1, a2, a3,
                     __float_as_uint(bb.x), __float_as_uint(bb.y));
        }
    }
}
// acc (nf,i): row(local16) = g+(i>>1)*8, col = wn*32+nf*8+2*tig+(i&1)

// 32-row warp tile (proj): rows wm*32..+32, cols wn*32..+32, one chunk16
template<int XST>
__device__ __forceinline__ void compute_chunk32(
    float (&c)[2][4][4], const float* Xs, int kkbase,
    const float* buf, int lane, int wn)
{
    int g = lane >> 2, tig = lane & 3;
    const float2* bf = (const float2*)buf;
#pragma unroll
    for (int ks = 0; ks < 2; ks++) {
        unsigned a[2][4];
#pragma unroll
        for (int mr = 0; mr < 2; mr++) {
            const float* xr  = Xs + (mr * 16 + g) * XST + kkbase + ks * 8;
            const float* xr8 = xr + 8 * XST;
            a[mr][0] = __float_as_uint(xr[tig]);
            a[mr][1] = __float_as_uint(xr8[tig]);
            a[mr][2] = __float_as_uint(xr[tig + 4]);
            a[mr][3] = __float_as_uint(xr8[tig + 4]);
        }
#pragma unroll
        for (int nf = 0; nf < 4; nf++) {
            float2 bb = bf[(ks * 16 + wn * 4 + nf) * 32 + g * 4 + tig];
#pragma unroll
            for (int mr = 0; mr < 2; mr++)
                mma_tf32(c[mr][nf], a[mr][0], a[mr][1], a[mr][2], a[mr][3],
                         __float_as_uint(bb.x), __float_as_uint(bb.y));
        }
    }
}

// ---------------- setup: edges + degree + scan + eb1 copy ---------------------
__global__ void setup_kernel(const void* __restrict__ eidx,
                             const float* __restrict__ eb1) {
    __shared__ int sflag;
    __shared__ int sdeg[NQv];
    int t = threadIdx.x;
    if (t < LLv) g_eb1c[t] = eb1[t];
    if (t == 0) {
        const long long* p = (const long long*)eidx;
        int ok = 1;
        for (int i = 0; i < 64; i++) {
            long long v = p[i];
            if (v < 0 || v >= NQv) { ok = 0; break; }
        }
        sflag = ok; g_is64 = ok;
    }
    __syncthreads();
    int is64 = sflag;
    for (int i = t; i < 2 * EEv; i += 1024) {
        int v = is64 ? (int)((const long long*)eidx)[i] : ((const int*)eidx)[i];
        if (i < EEv) g_src[i] = v;
        else         g_tgt[i - EEv] = v;
    }
    sdeg[t] = 0;
    __syncthreads();
    for (int e = t; e < EEv; e += 1024) atomicAdd(&sdeg[g_src[e]], 1);
    __syncthreads();
    for (int off = 1; off < NQv; off <<= 1) {
        int v = (t >= off) ? sdeg[t - off] : 0;
        __syncthreads();
        sdeg[t] += v;
        __syncthreads();
    }
    g_rowptr[t + 1] = sdeg[t];
    if (t == 0) g_rowptr[0] = 0;
}

// deterministic CSR fill (warp-per-node, order-preserving)
__global__ void fill_kernel(const float* __restrict__ eattr) {   // NQv/8 x 256
    __shared__ int ss[EEv];
    int t = threadIdx.x;
    for (int i = t; i < EEv; i += 256) ss[i] = g_src[i];
    __syncthreads();
    int lane = t & 31;
    int n = blockIdx.x * 8 + (t >> 5);
    int pos = g_rowptr[n];
    for (int base = 0; base < EEv; base += 32) {
        int v = ss[base + lane];
        unsigned m = __ballot_sync(0xffffffffu, v == n);
        if (v == n) {
            int ofs = __popc(m & ((1u << lane) - 1u));
            g_csr_tgt[pos + ofs] = g_tgt[base + lane];
            g_csr_ea[pos + ofs]  = eattr[base + lane];
        }
        pos += __popc(m);
    }
}

// fragment-pack (16-k chunks, float2 layout) + tf32-round weights; w1abT; w1c
__global__ void repack_kernel(const float* __restrict__ ew1,
                              const float* __restrict__ ew2,
                              const float* __restrict__ nw1,
                              const float* __restrict__ nw2) {
    int i = blockIdx.x * 256 + threadIdx.x;   // < 180480
    if (i >= 180480) return;
    if (i >= 180224) {                        // w1c: 256 entries
        int j = i - 180224;
        int kk = j >> 7, cc = j & 127;
        g_w1c[kk][cc] = ew1[(kk * 128 + cc) * 257 + 256];
        return;
    }
    if (i >= 163840) {                        // w1abT: [k][c]
        int j = i - 163840;
        int kidx = j >> 7, cc = j & 127;
        g_w1abT[j] = ew1[cc * 257 + kidx] + ew1[cc * 257 + 128 + kidx];
        return;
    }
    float* dst; int j; float val;
    if (i < 16384)       { dst = g_pw1a; j = i; }
    else if (i < 32768)  { dst = g_pw1b; j = i - 16384; }
    else if (i < 65536)  { int kk = (i - 32768) >> 14; dst = g_pew2[kk]; j = (i - 32768) & 16383; }
    else if (i < 131072) { int kk = (i - 65536) >> 15; dst = g_pnw1[kk]; j = (i - 65536) & 32767; }
    else                 { int kk = (i - 131072) >> 14; dst = g_pnw2[kk]; j = (i - 131072) & 16383; }
    // chunk16 layout: j = (((chunk*2 + ks)*16 + cg)*32 + g*4 + tig)*2 + p
    int p = j & 1, tig = (j >> 1) & 3, g = (j >> 3) & 7;
    int cg = (j >> 6) & 15, ks = (j >> 10) & 1, chunk = j >> 11;
    int row = cg * 8 + g;
    int k = chunk * 16 + ks * 8 + tig + 4 * p;
    if (i < 16384)       val = ew1[(128 + row) * 257 + k];
    else if (i < 32768)  val = ew1[(128 + row) * 257 + 128 + k];
    else if (i < 65536)  val = (ew2 + ((i - 32768) >> 14) * 16384)[row * 128 + k];
    else if (i < 131072) val = (nw1 + ((i - 65536) >> 15) * 32768)[row * 256 + k];
    else                 val = (nw2 + ((i - 131072) >> 14) * 16384)[row * 128 + k];
    dst[j] = f2tf32f(val);
}

// ---------------- fused per-round node kernel: persistent 4-tile CTAs --------
// grid (NQv/32, BB/4) = 512 CTAs (single wave at 4 CTAs/SM); each CTA runs
// 4 batch-tiles through the 32-chunk (16-k) ring-2 pipeline.
// xs aliases inp (phase-ordered, barrier-guarded). CSR gather from global.
// smem floats: inp/xs 8320 | wb 2x2048 | sbase 128 | rp 40  -> 50.3 KB
#define RK_FLOATS (8320 + 4096 + 128 + 40)
#define RK_SMEM (RK_FLOATS * 4)
__global__ __launch_bounds__(256) void round_kernel(
    const float* __restrict__ z0,
    const float* __restrict__ eb2,
    const float* __restrict__ nb1,
    const float* __restrict__ lng, const float* __restrict__ lnb,
    const float* __restrict__ nb2,
    int k)
{
    extern __shared__ float sm[];
    float* inp   = sm;                       // [32][260] (GEMM2 input view)
    float* xs    = sm;                       // [32][132] ALIAS (GEMM1/3 view)
    float* wb    = sm + 8320;                // 2 x 2048
    float* sbase = wb + 4096;                // [128]
    int*   rp    = (int*)(sbase + 128);      // [33]

    const float* pew2 = g_pew2[k];
    const float* pnw1 = g_pnw1[k];
    const float* pnw2 = g_pnw2[k];

    int q0 = blockIdx.x * 32, t = threadIdx.x;
    int lane = t & 31, w = t >> 5;            // 8 warps
    int g = lane >> 2, tig = lane & 3;
    int wm = w & 1, wn = w >> 1;              // rows 16*wm, cols 32*wn

    auto wchunk = [&](int ci) -> const float* {
        return ci < 8  ? pew2 + ci * 2048
             : ci < 24 ? pnw1 + (ci - 8) * 2048
             :           pnw2 + (ci - 24) * 2048;
    };

#pragma unroll 1
    for (int it = 0; it < 4; it++) {
        int b = blockIdx.y * 4 + it;
        int rowbase = (b * NQv + q0) * LLv;

        // safe vs previous tile: rp/sbase/wb(buf0) do not alias xs, and all
        // warps passed the ci==31 barrier (so buf0 + xs reads are complete
        // before the barrier below lets stage-1 overwrite xs).
        pf_chunk<256>(wb, wchunk(0), t);      // chunk 0 -> buf 0

        if (t < 33) rp[t] = g_rowptr[q0 + t];

        if (k == 0 && t < LLv) {  // in-block base[b] = z0[b]·(W1a+W1b)^T + eb1
            float a0 = 0.f, a1 = 0.f, a2 = 0.f, a3 = 0.f;
            const float* zr = z0 + b * LLv;
#pragma unroll 4
            for (int kk = 0; kk < LLv; kk += 4) {
                a0 = fmaf(__ldg(zr + kk),     g_w1abT[(kk)     * LLv + t], a0);
                a1 = fmaf(__ldg(zr + kk + 1), g_w1abT[(kk + 1) * LLv + t], a1);
                a2 = fmaf(__ldg(zr + kk + 2), g_w1abT[(kk + 2) * LLv + t], a2);
                a3 = fmaf(__ldg(zr + kk + 3), g_w1abT[(kk + 3) * LLv + t], a3);
            }
            sbase[t] = (a0 + a1) + (a2 + a3) + g_eb1c[t];
        }
        __syncthreads();

        // ---- stage 1: hid_agg[n] = sum_{e: src=n} relu(A[n]+B[tgt]+ea*w1c) --
        {
            float4 w1c4 = ((const float4*)&g_w1c[k][0])[lane];
#pragma unroll
            for (int j = 0; j < 4; j++) {
                int r = w * 4 + j;
                float4 a4;
                if (k == 0) a4 = ((const float4*)sbase)[lane];
                else        a4 = ((const float4*)(g_A + rowbase + r * LLv))[lane];
                float4 acc = make_float4(0.f, 0.f, 0.f, 0.f);
                int e0 = rp[r], e1 = rp[r + 1];
                if (k == 0) {
                    for (int e = e0; e < e1; e++) {
                        float ea = __ldg(g_csr_ea + e);
                        acc.x += fmaxf(fmaf(ea, w1c4.x, a4.x), 0.f);
                        acc.y += fmaxf(fmaf(ea, w1c4.y, a4.y), 0.f);
                        acc.z += fmaxf(fmaf(ea, w1c4.z, a4.z), 0.f);
                        acc.w += fmaxf(fmaf(ea, w1c4.w, a4.w), 0.f);
                    }
                } else {
                    for (int e = e0; e < e1; e++) {
                        float ea = __ldg(g_csr_ea + e);
                        int tg = __ldg(g_csr_tgt + e);
                        float4 bv = ((const float4*)(g_Bv + (b * NQv + tg) * LLv))[lane];
                        acc.x += fmaxf(fmaf(ea, w1c4.x, a4.x + bv.x), 0.f);
                        acc.y += fmaxf(fmaf(ea, w1c4.y, a4.y + bv.y), 0.f);
                        acc.z += fmaxf(fmaf(ea, w1c4.z, a4.z + bv.z), 0.f);
                        acc.w += fmaxf(fmaf(ea, w1c4.w, a4.w + bv.w), 0.f);
                    }
                }
                float* d = &xs[r * 132 + lane * 4];
                d[0] = f2tf32f(acc.x); d[1] = f2tf32f(acc.y);
                d[2] = f2tf32f(acc.z); d[3] = f2tf32f(acc.w);
            }
        }

        float c[4][4];
        zacc4(c);

        // ---- unified 32-chunk ring-2 pipeline ----
#pragma unroll 1
        for (int ci = 0; ci < 32; ci++) {
            cpa_wait<0>();                    // chunk ci landed (sole group)
            __syncthreads();                  // + all warps done with ci-1
            if (ci + 1 < 32)
                pf_chunk<256>(wb + ((ci + 1) & 1) * 2048, wchunk(ci + 1), t);

            if (ci < 8)
                compute_chunk16<132>(c, xs + wm * 16 * 132, ci * 16,
                                     wb + (ci & 1) * 2048, lane, wn);
            else if (ci < 24)
                compute_chunk16<260>(c, inp + wm * 16 * 260, (ci - 8) * 16,
                                     wb + (ci & 1) * 2048, lane, wn);
            else
                compute_chunk16<132>(c, xs + wm * 16 * 132, (ci - 24) * 16,
                                     wb + (ci & 1) * 2048, lane, wn);

            if (ci == 7) {
                __syncthreads();              // all warps done reading xs view
#pragma unroll
                for (int nf = 0; nf < 4; nf++)
#pragma unroll
                    for (int i = 0; i < 4; i++) {
                        int row = wm * 16 + g + (i >> 1) * 8;
                        int col = wn * 32 + nf * 8 + 2 * tig + (i & 1);
                        float dg = (float)(rp[row + 1] - rp[row]);
                        inp[row * 260 + 128 + col] =
                            f2tf32f(c[nf][i] + dg * eb2[col]);
                    }
#pragma unroll
                for (int i = 0; i < 4; i++) {
                    int idx = i * 256 + t;             // 1024 float4 / 32x128
                    int r = idx >> 5, j4 = idx & 31;
                    float4 v = (k == 0)
                        ? ((const float4*)(z0 + b * LLv))[j4]
                        : ((const float4*)(g_h + rowbase + r * LLv))[j4];
                    float* d = &inp[r * 260 + j4 * 4];
                    d[0] = f2tf32f(v.x); d[1] = f2tf32f(v.y);
                    d[2] = f2tf32f(v.z); d[3] = f2tf32f(v.w);
                }
                zacc4(c);
            }
            if (ci == 23) {
                __syncthreads();              // all warps done reading inp view
#pragma unroll
                for (int nf = 0; nf < 4; nf++)
#pragma unroll
                    for (int i = 0; i < 4; i++) {
                        int row = wm * 16 + g + (i >> 1) * 8;
                        int col = wn * 32 + nf * 8 + 2 * tig + (i & 1);
                        xs[row * 132 + col] = fmaxf(c[nf][i] + nb1[col], 0.f);
                    }
                __syncthreads();
#pragma unroll
                for (int j = 0; j < 4; j++) {
                    int q = w * 4 + j;
                    float v0 = xs[q * 132 + lane];
                    float v1 = xs[q * 132 + lane + 32];
                    float v2 = xs[q * 132 + lane + 64];
                    float v3 = xs[q * 132 + lane + 96];
                    float s = v0 + v1 + v2 + v3;
#pragma unroll
                    for (int o = 16; o; o >>= 1)
                        s += __shfl_xor_sync(0xffffffffu, s, o);
                    float mu = s * (1.f / 128.f);
                    float d0 = v0 - mu, d1 = v1 - mu;
                    float d2 = v2 - mu, d3 = v3 - mu;
                    float s2 = d0 * d0 + d1 * d1 + d2 * d2 + d3 * d3;
#pragma unroll
                    for (int o = 16; o; o >>= 1)
                        s2 += __shfl_xor_sync(0xffffffffu, s2, o);
                    float rstd = rsqrtf(s2 * (1.f / 128.f) + 1e-5f);
                    xs[q * 132 + lane] =
                        f2tf32f(d0 * rstd * lng[lane]      + lnb[lane]);
                    xs[q * 132 + lane + 32] =
                        f2tf32f(d1 * rstd * lng[lane + 32] + lnb[lane + 32]);
                    xs[q * 132 + lane + 64] =
                        f2tf32f(d2 * rstd * lng[lane + 64] + lnb[lane + 64]);
                    xs[q * 132 + lane + 96] =
                        f2tf32f(d3 * rstd * lng[lane + 96] + lnb[lane + 96]);
                }
                zacc4(c);
                __syncthreads();              // LN writes visible to GEMM3
            }
        }

#pragma unroll
        for (int nf = 0; nf < 4; nf++)
#pragma unroll
            for (int i = 0; i < 4; i++) {
                int row = wm * 16 + g + (i >> 1) * 8;
                int col = wn * 32 + nf * 8 + 2 * tig + (i & 1);
                float res = (k == 0) ? z0[b * LLv + col]
                                     : g_h[rowbase + row * LLv + col];
                g_h[rowbase + row * LLv + col] = res + c[nf][i] + nb2[col];
            }
    }
}

// ---------------- round-1 per-node projections (persistent 2-tile CTAs) ------
#define PJ_SMEM ((64 * 132 + 2 * 2048) * 4)
__global__ __launch_bounds__(256) void proj_kernel(const float* __restrict__ eb1) {
    extern __shared__ float sm[];
    float* Xh  = sm;                 // [64][132]
    float* wb  = sm + 64 * 132;      // 2 x 2048

    int t = threadIdx.x;
    int lane = t & 31, w = t >> 5;
    int g = lane >> 2, tig = lane & 3;
    int wm = w & 1, wn = w >> 1;

    auto wchunk = [&](int ci) -> const float* {
        return ci < 8 ? g_pw1a + ci * 2048 : g_pw1b + (ci - 8) * 2048;
    };

#pragma unroll 1
    for (int it = 0; it < 2; it++) {
        int r0 = (blockIdx.x * 2 + it) * 64;

        __syncthreads();                      // prev tile's Xh reads complete
        pf_chunk<256>(wb, wchunk(0), t);

#pragma unroll
        for (int i = 0; i < 8; i++) {
            int idx = i * 256 + t;
            int r = idx >> 5, j4 = idx & 31;
            float4 v = ((const float4*)(g_h + (r0 + r) * LLv))[j4];
            float* d = &Xh[r * 132 + j4 * 4];
            d[0] = f2tf32f(v.x); d[1] = f2tf32f(v.y);
            d[2] = f2tf32f(v.z); d[3] = f2tf32f(v.w);
        }

        float c[2][4][4];
        zacc2(c);
#pragma unroll 1
        for (int ci = 0; ci < 16; ci++) {
            cpa_wait<0>();
            __syncthreads();
            if (ci + 1 < 16)
                pf_chunk<256>(wb + ((ci + 1) & 1) * 2048, wchunk(ci + 1), t);
            compute_chunk32<132>(c, Xh + wm * 32 * 132, (ci & 7) * 16,
                                 wb + (ci & 1) * 2048, lane, wn);
            if (ci == 7) {
#pragma unroll
                for (int mr = 0; mr < 2; mr++)
#pragma unroll
                    for (int nf = 0; nf < 4; nf++)
#pragma unroll
                        for (int i = 0; i < 4; i++) {
                            int row = wm * 32 + mr * 16 + g + (i >> 1) * 8;
                            int col = wn * 32 + nf * 8 + 2 * tig + (i & 1);
                            g_A[(r0 + row) * LLv + col] = c[mr][nf][i] + eb1[col];
                        }
                zacc2(c);
            }
        }
#pragma unroll
        for (int mr = 0; mr < 2; mr++)
#pragma unroll
            for (int nf = 0; nf < 4; nf++)
#pragma unroll
                for (int i = 0; i < 4; i++) {
                    int row = wm * 32 + mr * 16 + g + (i >> 1) * 8;
                    int col = wn * 32 + nf * 8 + 2 * tig + (i & 1);
                    g_Bv[(r0 + row) * LLv + col] = c[mr][nf][i];
                }
    }
}

// ---------------- final mean over nodes --------------------------------------
__global__ void mean_kernel(float* __restrict__ out) {
    int b = blockIdx.x, t = threadIdx.x;   // 512 threads
    int l = t & 127, seg = t >> 7;
    const float* p = g_h + (b * NQv + seg * 256) * LLv + l;
    float s = 0.f;
#pragma unroll 8
    for (int q = 0; q < 256; q++) s += p[q * LLv];
    __shared__ float red[4][LLv];
    red[seg][l] = s;
    __syncthreads();
    if (seg == 0)
        out[b * LLv + l] =
            (red[0][l] + red[1][l] + red[2][l] + red[3][l]) * (1.f / 1024.f);
}

// ---------------- launch ------------------------------------------------------
extern "C" void kernel_launch(void* const* d_in, const int* in_sizes, int n_in,
                              void* d_out, int out_size) {
    const float* z0    = (const float*)d_in[0];
    const void*  eidx  = d_in[1];
    const float* eattr = (const float*)d_in[2];
    const float* ew1 = (const float*)d_in[4];
    const float* eb1 = (const float*)d_in[5];
    const float* ew2 = (const float*)d_in[6];
    const float* eb2 = (const float*)d_in[7];
    const float* nw1 = (const float*)d_in[8];
    const float* nb1 = (const float*)d_in[9];
    const float* lng = (const float*)d_in[10];
    const float* lnb = (const float*)d_in[11];
    const float* nw2 = (const float*)d_in[12];
    const float* nb2 = (const float*)d_in[13];
    float* out = (float*)d_out;

    cudaFuncSetAttribute(round_kernel,
        cudaFuncAttributeMaxDynamicSharedMemorySize, RK_SMEM);
    cudaFuncSetAttribute(proj_kernel,
        cudaFuncAttributeMaxDynamicSharedMemorySize, PJ_SMEM);

    setup_kernel<<<1, 1024>>>(eidx, eb1);
    fill_kernel<<<NQv / 8, 256>>>(eattr);
    repack_kernel<<<705, 256>>>(ew1, ew2, nw1, nw2);

    round_kernel<<<dim3(NQv / 32, BB / 4), 256, RK_SMEM>>>(   // launch index 3
        z0, eb2, nb1, lng, lnb, nb2, 0);

    proj_kernel<<<BB * NQv / 128, 256, PJ_SMEM>>>(eb1 + 128);
    round_kernel<<<dim3(NQv / 32, BB / 4), 256, RK_SMEM>>>(
        z0, eb2 + LLv, nb1 + LLv,
        lng + LLv, lnb + LLv, nb2 + LLv, 1);

    mean_kernel<<<BB, 512>>>(out);
}

// round 14
// speedup vs baseline: 1.2100x; 1.2100x over previous
#include <cuda_runtime.h>

#define BB 64
#define NQv 1024
#define LLv 128
#define EEv 8192

// ---------------- scratch (static device globals; no allocations) ----------
__device__ float g_h[BB * NQv * LLv];      // node states (exact fp32)
__device__ float g_A[BB * NQv * LLv];      // h @ W1a^T + b1   (round 1)
__device__ float g_Bv[BB * NQv * LLv];     // h @ W1b^T        (round 1)
__device__ float g_w1abT[LLv * LLv];       // (w1a[0]+w1b[0])^T  [k][c]
__device__ float g_w1c[2][LLv];            // e_w1[:, :, 256]
__device__ float g_eb1c[LLv];              // e_b1[0] copy (base bias)
__device__ float g_part[BB * 4 * LLv];     // mean partials
// fragment-packed tf32 weights: chunk16 = 2048 floats (16 k x 128 cols),
// float2 fragment layout: j = (((chunk*2+ks)*16+cg)*32 + g*4+tig)*2 + p
__device__ __align__(16) float g_pw1a[16384], g_pw1b[16384];
__device__ __align__(16) float g_pew2[2][16384];
__device__ __align__(16) float g_pnw1[2][32768];
__device__ __align__(16) float g_pnw2[2][16384];
__device__ int   g_src[EEv];
__device__ int   g_tgt[EEv];
__device__ int   g_rowptr[NQv + 1];
__device__ int   g_csr_tgt[EEv];
__device__ float g_csr_ea[EEv];
__device__ int   g_is64;

// ---------------- tf32 / mma / cp.async helpers ------------------------------
__device__ __forceinline__ float f2tf32f(float x) {
    unsigned r;
    asm("cvt.rna.tf32.f32 %0, %1;" : "=r"(r) : "f"(x));
    return __uint_as_float(r);
}
__device__ __forceinline__ void mma_tf32(float (&c)[4],
    unsigned a0, unsigned a1, unsigned a2, unsigned a3,
    unsigned b0, unsigned b1)
{
    asm volatile(
        "mma.sync.aligned.m16n8k8.row.col.f32.tf32.tf32.f32 "
        "{%0,%1,%2,%3}, {%4,%5,%6,%7}, {%8,%9}, {%0,%1,%2,%3};"
        : "+f"(c[0]), "+f"(c[1]), "+f"(c[2]), "+f"(c[3])
        : "r"(a0), "r"(a1), "r"(a2), "r"(a3), "r"(b0), "r"(b1));
}
__device__ __forceinline__ void zacc4(float (&c)[4][4]) {
#pragma unroll
    for (int b = 0; b < 4; b++)
#pragma unroll
        for (int i = 0; i < 4; i++) c[b][i] = 0.f;
}
__device__ __forceinline__ void zacc2(float (&c)[2][4][4]) {
#pragma unroll
    for (int a = 0; a < 2; a++)
#pragma unroll
        for (int b = 0; b < 4; b++)
#pragma unroll
            for (int i = 0; i < 4; i++) c[a][b][i] = 0.f;
}
__device__ __forceinline__ void cpa16(float* dst, const float* src) {
    unsigned d = (unsigned)__cvta_generic_to_shared(dst);
    asm volatile("cp.async.cg.shared.global [%0], [%1], 16;" :: "r"(d), "l"(src));
}
__device__ __forceinline__ void cpa_commit() {
    asm volatile("cp.async.commit_group;" ::: "memory");
}
template<int N> __device__ __forceinline__ void cpa_wait() {
    asm volatile("cp.async.wait_group %0;" :: "n"(N) : "memory");
}
// 16-k weight chunk = 2048 floats
template<int NT>
__device__ __forceinline__ void pf_chunk(float* buf, const float* Wp, int t) {
#pragma unroll
    for (int i = 0; i < 2048 / (4 * NT); i++)
        cpa16(buf + (i * NT + t) * 4, Wp + (i * NT + t) * 4);
    cpa_commit();
}

// 16-row warp tile: C[16][32] += Xs(16 rows) @ W^T cols [wn*32,+32), one chunk16
template<int XST>
__device__ __forceinline__ void compute_chunk16(
    float (&c)[4][4], const float* Xs, int kkbase,
    const float* buf, int lane, int wn)
{
    int g = lane >> 2, tig = lane & 3;
    const float2* bf = (const float2*)buf;
#pragma unroll
    for (int ks = 0; ks < 2; ks++) {
        const float* xr  = Xs + g * XST + kkbase + ks * 8;
        const float* xr8 = xr + 8 * XST;
        unsigned a0 = __float_as_uint(xr[tig]);
        unsigned a1 = __float_as_uint(xr8[tig]);
        unsigned a2 = __float_as_uint(xr[tig + 4]);
        unsigned a3 = __float_as_uint(xr8[tig + 4]);
#pragma unroll
        for (int nf = 0; nf < 4; nf++) {
            float2 bb = bf[(ks * 16 + wn * 4 + nf) * 32 + g * 4 + tig];
            mma_tf32(c[nf], a0, a1, a2, a3,
                     __float_as_uint(bb.x), __float_as_uint(bb.y));
        }
    }
}
// acc (nf,i): row(local16) = g+(i>>1)*8, col = wn*32+nf*8+2*tig+(i&1)

// 32-row warp tile (proj): rows wm*32..+32, cols wn*32..+32, one chunk16
template<int XST>
__device__ __forceinline__ void compute_chunk32(
    float (&c)[2][4][4], const float* Xs, int kkbase,
    const float* buf, int lane, int wn)
{
    int g = lane >> 2, tig = lane & 3;
    const float2* bf = (const float2*)buf;
#pragma unroll
    for (int ks = 0; ks < 2; ks++) {
        unsigned a[2][4];
#pragma unroll
        for (int mr = 0; mr < 2; mr++) {
            const float* xr  = Xs + (mr * 16 + g) * XST + kkbase + ks * 8;
            const float* xr8 = xr + 8 * XST;
            a[mr][0] = __float_as_uint(xr[tig]);
            a[mr][1] = __float_as_uint(xr8[tig]);
            a[mr][2] = __float_as_uint(xr[tig + 4]);
            a[mr][3] = __float_as_uint(xr8[tig + 4]);
        }
#pragma unroll
        for (int nf = 0; nf < 4; nf++) {
            float2 bb = bf[(ks * 16 + wn * 4 + nf) * 32 + g * 4 + tig];
#pragma unroll
            for (int mr = 0; mr < 2; mr++)
                mma_tf32(c[mr][nf], a[mr][0], a[mr][1], a[mr][2], a[mr][3],
                         __float_as_uint(bb.x), __float_as_uint(bb.y));
        }
    }
}

// ---------------- setup: edges + degree + scan + eb1 copy ---------------------
__global__ void setup_kernel(const void* __restrict__ eidx,
                             const float* __restrict__ eb1) {
    __shared__ int sflag;
    __shared__ int sdeg[NQv];
    int t = threadIdx.x;
    if (t < LLv) g_eb1c[t] = eb1[t];
    if (t == 0) {
        const long long* p = (const long long*)eidx;
        int ok = 1;
        for (int i = 0; i < 64; i++) {
            long long v = p[i];
            if (v < 0 || v >= NQv) { ok = 0; break; }
        }
        sflag = ok; g_is64 = ok;
    }
    __syncthreads();
    int is64 = sflag;
    for (int i = t; i < 2 * EEv; i += 1024) {
        int v = is64 ? (int)((const long long*)eidx)[i] : ((const int*)eidx)[i];
        if (i < EEv) g_src[i] = v;
        else         g_tgt[i - EEv] = v;
    }
    sdeg[t] = 0;
    __syncthreads();
    for (int e = t; e < EEv; e += 1024) atomicAdd(&sdeg[g_src[e]], 1);
    __syncthreads();
    for (int off = 1; off < NQv; off <<= 1) {
        int v = (t >= off) ? sdeg[t - off] : 0;
        __syncthreads();
        sdeg[t] += v;
        __syncthreads();
    }
    g_rowptr[t + 1] = sdeg[t];
    if (t == 0) g_rowptr[0] = 0;
}

// deterministic CSR fill (warp-per-node, order-preserving)
__global__ void fill_kernel(const float* __restrict__ eattr) {   // NQv/8 x 256
    __shared__ int ss[EEv];
    int t = threadIdx.x;
    for (int i = t; i < EEv; i += 256) ss[i] = g_src[i];
    __syncthreads();
    int lane = t & 31;
    int n = blockIdx.x * 8 + (t >> 5);
    int pos = g_rowptr[n];
    for (int base = 0; base < EEv; base += 32) {
        int v = ss[base + lane];
        unsigned m = __ballot_sync(0xffffffffu, v == n);
        if (v == n) {
            int ofs = __popc(m & ((1u << lane) - 1u));
            g_csr_tgt[pos + ofs] = g_tgt[base + lane];
            g_csr_ea[pos + ofs]  = eattr[base + lane];
        }
        pos += __popc(m);
    }
}

// fragment-pack (16-k chunks, float2 layout) + tf32-round weights; w1abT; w1c
__global__ void repack_kernel(const float* __restrict__ ew1,
                              const float* __restrict__ ew2,
                              const float* __restrict__ nw1,
                              const float* __restrict__ nw2) {
    int i = blockIdx.x * 256 + threadIdx.x;   // < 180480
    if (i >= 180480) return;
    if (i >= 180224) {                        // w1c: 256 entries
        int j = i - 180224;
        int kk = j >> 7, cc = j & 127;
        g_w1c[kk][cc] = ew1[(kk * 128 + cc) * 257 + 256];
        return;
    }
    if (i >= 163840) {                        // w1abT: [k][c]
        int j = i - 163840;
        int kidx = j >> 7, cc = j & 127;
        g_w1abT[j] = ew1[cc * 257 + kidx] + ew1[cc * 257 + 128 + kidx];
        return;
    }
    float* dst; int j; float val;
    if (i < 16384)       { dst = g_pw1a; j = i; }
    else if (i < 32768)  { dst = g_pw1b; j = i - 16384; }
    else if (i < 65536)  { int kk = (i - 32768) >> 14; dst = g_pew2[kk]; j = (i - 32768) & 16383; }
    else if (i < 131072) { int kk = (i - 65536) >> 15; dst = g_pnw1[kk]; j = (i - 65536) & 32767; }
    else                 { int kk = (i - 131072) >> 14; dst = g_pnw2[kk]; j = (i - 131072) & 16383; }
    // chunk16 layout: j = (((chunk*2 + ks)*16 + cg)*32 + g*4 + tig)*2 + p
    int p = j & 1, tig = (j >> 1) & 3, g = (j >> 3) & 7;
    int cg = (j >> 6) & 15, ks = (j >> 10) & 1, chunk = j >> 11;
    int row = cg * 8 + g;
    int k = chunk * 16 + ks * 8 + tig + 4 * p;
    if (i < 16384)       val = ew1[(128 + row) * 257 + k];
    else if (i < 32768)  val = ew1[(128 + row) * 257 + 128 + k];
    else if (i < 65536)  val = (ew2 + ((i - 32768) >> 14) * 16384)[row * 128 + k];
    else if (i < 131072) val = (nw1 + ((i - 65536) >> 15) * 32768)[row * 256 + k];
    else                 val = (nw2 + ((i - 131072) >> 14) * 16384)[row * 128 + k];
    dst[j] = f2tf32f(val);
}

// ---------------- fused per-round node kernel: 32 rows, 256 threads ----------
// 32-chunk (16-k) ring-2: GEMM1(0-7) GEMM2(8-23) GEMM3(24-31).
// xs aliases inp (phase-ordered, barrier-guarded). CSR gather from global.
// smem floats: inp/xs 8320 | wb 2x2048 | sbase 128 | rp 40  -> 50.3 KB
#define RK_FLOATS (8320 + 4096 + 128 + 40)
#define RK_SMEM (RK_FLOATS * 4)
__global__ __launch_bounds__(256) void round_kernel(
    const float* __restrict__ z0,
    const float* __restrict__ eb2,
    const float* __restrict__ nb1,
    const float* __restrict__ lng, const float* __restrict__ lnb,
    const float* __restrict__ nb2,
    int k)
{
    extern __shared__ float sm[];
    float* inp   = sm;                       // [32][260] (GEMM2 input view)
    float* xs    = sm;                       // [32][132] ALIAS (GEMM1/3 view)
    float* wb    = sm + 8320;                // 2 x 2048
    float* sbase = wb + 4096;                // [128]
    int*   rp    = (int*)(sbase + 128);      // [33]

    const float* pew2 = g_pew2[k];
    const float* pnw1 = g_pnw1[k];
    const float* pnw2 = g_pnw2[k];

    int b = blockIdx.y, q0 = blockIdx.x * 32, t = threadIdx.x;
    int rowbase = (b * NQv + q0) * LLv;
    int lane = t & 31, w = t >> 5;            // 8 warps
    int g = lane >> 2, tig = lane & 3;
    int wm = w & 1, wn = w >> 1;              // rows 16*wm, cols 32*wn

    auto wchunk = [&](int ci) -> const float* {
        return ci < 8  ? pew2 + ci * 2048
             : ci < 24 ? pnw1 + (ci - 8) * 2048
             :           pnw2 + (ci - 24) * 2048;
    };

    pf_chunk<256>(wb, wchunk(0), t);          // chunk 0 -> buf 0

    if (t < 33) rp[t] = g_rowptr[q0 + t];

    if (k == 0 && t < LLv) {   // in-block base[b] = z0[b]·(W1a+W1b)^T + eb1
        float a0 = 0.f, a1 = 0.f, a2 = 0.f, a3 = 0.f;
        const float* zr = z0 + b * LLv;
#pragma unroll 4
        for (int kk = 0; kk < LLv; kk += 4) {
            a0 = fmaf(__ldg(zr + kk),     g_w1abT[(kk)     * LLv + t], a0);
            a1 = fmaf(__ldg(zr + kk + 1), g_w1abT[(kk + 1) * LLv + t], a1);
            a2 = fmaf(__ldg(zr + kk + 2), g_w1abT[(kk + 2) * LLv + t], a2);
            a3 = fmaf(__ldg(zr + kk + 3), g_w1abT[(kk + 3) * LLv + t], a3);
        }
        sbase[t] = (a0 + a1) + (a2 + a3) + g_eb1c[t];
    }
    __syncthreads();

    // ---- stage 1: hid_agg[n] = sum_{e: src=n} relu(A[n]+B[tgt]+ea*w1c) ----
    {
        float4 w1c4 = ((const float4*)&g_w1c[k][0])[lane];
#pragma unroll
        for (int j = 0; j < 4; j++) {
            int r = w * 4 + j;
            float4 a4;
            if (k == 0) a4 = ((const float4*)sbase)[lane];
            else        a4 = ((const float4*)(g_A + rowbase + r * LLv))[lane];
            float4 acc = make_float4(0.f, 0.f, 0.f, 0.f);
            int e0 = rp[r], e1 = rp[r + 1];
            if (k == 0) {
                for (int e = e0; e < e1; e++) {
                    float ea = __ldg(g_csr_ea + e);
                    acc.x += fmaxf(fmaf(ea, w1c4.x, a4.x), 0.f);
                    acc.y += fmaxf(fmaf(ea, w1c4.y, a4.y), 0.f);
                    acc.z += fmaxf(fmaf(ea, w1c4.z, a4.z), 0.f);
                    acc.w += fmaxf(fmaf(ea, w1c4.w, a4.w), 0.f);
                }
            } else {
                for (int e = e0; e < e1; e++) {
                    float ea = __ldg(g_csr_ea + e);
                    int tg = __ldg(g_csr_tgt + e);
                    float4 bv = ((const float4*)(g_Bv + (b * NQv + tg) * LLv))[lane];
                    acc.x += fmaxf(fmaf(ea, w1c4.x, a4.x + bv.x), 0.f);
                    acc.y += fmaxf(fmaf(ea, w1c4.y, a4.y + bv.y), 0.f);
                    acc.z += fmaxf(fmaf(ea, w1c4.z, a4.z + bv.z), 0.f);
                    acc.w += fmaxf(fmaf(ea, w1c4.w, a4.w + bv.w), 0.f);
                }
            }
            float* d = &xs[r * 132 + lane * 4];
            d[0] = f2tf32f(acc.x); d[1] = f2tf32f(acc.y);
            d[2] = f2tf32f(acc.z); d[3] = f2tf32f(acc.w);
        }
    }

    float c[4][4];
    zacc4(c);

    // ---- unified 32-chunk ring-2 pipeline ----
#pragma unroll 1
    for (int ci = 0; ci < 32; ci++) {
        cpa_wait<0>();                        // chunk ci landed (sole group)
        __syncthreads();                      // + all warps done with ci-1
        if (ci + 1 < 32)
            pf_chunk<256>(wb + ((ci + 1) & 1) * 2048, wchunk(ci + 1), t);

        if (ci < 8)
            compute_chunk16<132>(c, xs + wm * 16 * 132, ci * 16,
                                 wb + (ci & 1) * 2048, lane, wn);
        else if (ci < 24)
            compute_chunk16<260>(c, inp + wm * 16 * 260, (ci - 8) * 16,
                                 wb + (ci & 1) * 2048, lane, wn);
        else
            compute_chunk16<132>(c, xs + wm * 16 * 132, (ci - 24) * 16,
                                 wb + (ci & 1) * 2048, lane, wn);

        if (ci == 7) {
            __syncthreads();                  // all warps done reading xs view
#pragma unroll
            for (int nf = 0; nf < 4; nf++)
#pragma unroll
                for (int i = 0; i < 4; i++) {
                    int row = wm * 16 + g + (i >> 1) * 8;
                    int col = wn * 32 + nf * 8 + 2 * tig + (i & 1);
                    float dg = (float)(rp[row + 1] - rp[row]);
                    inp[row * 260 + 128 + col] =
                        f2tf32f(c[nf][i] + dg * eb2[col]);
                }
#pragma unroll
            for (int i = 0; i < 4; i++) {
                int idx = i * 256 + t;                 // 1024 float4 / 32x128
                int r = idx >> 5, j4 = idx & 31;
                float4 v = (k == 0) ? ((const float4*)(z0 + b * LLv))[j4]
                                    : ((const float4*)(g_h + rowbase + r * LLv))[j4];
                float* d = &inp[r * 260 + j4 * 4];
                d[0] = f2tf32f(v.x); d[1] = f2tf32f(v.y);
                d[2] = f2tf32f(v.z); d[3] = f2tf32f(v.w);
            }
            zacc4(c);
        }
        if (ci == 23) {
            __syncthreads();                  // all warps done reading inp view
#pragma unroll
            for (int nf = 0; nf < 4; nf++)
#pragma unroll
                for (int i = 0; i < 4; i++) {
                    int row = wm * 16 + g + (i >> 1) * 8;
                    int col = wn * 32 + nf * 8 + 2 * tig + (i & 1);
                    xs[row * 132 + col] = fmaxf(c[nf][i] + nb1[col], 0.f);
                }
            __syncthreads();
#pragma unroll
            for (int j = 0; j < 4; j++) {
                int q = w * 4 + j;
                float v0 = xs[q * 132 + lane],      v1 = xs[q * 132 + lane + 32];
                float v2 = xs[q * 132 + lane + 64], v3 = xs[q * 132 + lane + 96];
                float s = v0 + v1 + v2 + v3;
#pragma unroll
                for (int o = 16; o; o >>= 1) s += __shfl_xor_sync(0xffffffffu, s, o);
                float mu = s * (1.f / 128.f);
                float d0 = v0 - mu, d1 = v1 - mu, d2 = v2 - mu, d3 = v3 - mu;
                float s2 = d0 * d0 + d1 * d1 + d2 * d2 + d3 * d3;
#pragma unroll
                for (int o = 16; o; o >>= 1) s2 += __shfl_xor_sync(0xffffffffu, s2, o);
                float rstd = rsqrtf(s2 * (1.f / 128.f) + 1e-5f);
                xs[q * 132 + lane]      = f2tf32f(d0 * rstd * lng[lane]      + lnb[lane]);
                xs[q * 132 + lane + 32] = f2tf32f(d1 * rstd * lng[lane + 32] + lnb[lane + 32]);
                xs[q * 132 + lane + 64] = f2tf32f(d2 * rstd * lng[lane + 64] + lnb[lane + 64]);
                xs[q * 132 + lane + 96] = f2tf32f(d3 * rstd * lng[lane + 96] + lnb[lane + 96]);
            }
            zacc4(c);
            __syncthreads();                  // LN writes visible to GEMM3
        }
    }

#pragma unroll
    for (int nf = 0; nf < 4; nf++)
#pragma unroll
        for (int i = 0; i < 4; i++) {
            int row = wm * 16 + g + (i >> 1) * 8;
            int col = wn * 32 + nf * 8 + 2 * tig + (i & 1);
            float res = (k == 0) ? z0[b * LLv + col]
                                 : g_h[rowbase + row * LLv + col];
            g_h[rowbase + row * LLv + col] = res + c[nf][i] + nb2[col];
        }
}

// ---------------- round-1 per-node projections (16-k ring-2) ------------------
#define PJ_SMEM ((64 * 132 + 2 * 2048) * 4)
__global__ __launch_bounds__(256) void proj_kernel(const float* __restrict__ eb1) {
    extern __shared__ float sm[];
    float* Xh  = sm;                 // [64][132]
    float* wb  = sm + 64 * 132;      // 2 x 2048

    int r0 = blockIdx.x * 64, t = threadIdx.x;
    int lane = t & 31, w = t >> 5;
    int g = lane >> 2, tig = lane & 3;
    int wm = w & 1, wn = w >> 1;

    auto wchunk = [&](int ci) -> const float* {
        return ci < 8 ? g_pw1a + ci * 2048 : g_pw1b + (ci - 8) * 2048;
    };
    pf_chunk<256>(wb, wchunk(0), t);

#pragma unroll
    for (int i = 0; i < 8; i++) {
        int idx = i * 256 + t;
        int r = idx >> 5, j4 = idx & 31;
        float4 v = ((const float4*)(g_h + (r0 + r) * LLv))[j4];
        float* d = &Xh[r * 132 + j4 * 4];
        d[0] = f2tf32f(v.x); d[1] = f2tf32f(v.y);
        d[2] = f2tf32f(v.z); d[3] = f2tf32f(v.w);
    }

    float c[2][4][4];
    zacc2(c);
#pragma unroll 1
    for (int ci = 0; ci < 16; ci++) {
        cpa_wait<0>();
        __syncthreads();
        if (ci + 1 < 16)
            pf_chunk<256>(wb + ((ci + 1) & 1) * 2048, wchunk(ci + 1), t);
        compute_chunk32<132>(c, Xh + wm * 32 * 132, (ci & 7) * 16,
                             wb + (ci & 1) * 2048, lane, wn);
        if (ci == 7) {
#pragma unroll
            for (int mr = 0; mr < 2; mr++)
#pragma unroll
                for (int nf = 0; nf < 4; nf++)
#pragma unroll
                    for (int i = 0; i < 4; i++) {
                        int row = wm * 32 + mr * 16 + g + (i >> 1) * 8;
                        int col = wn * 32 + nf * 8 + 2 * tig + (i & 1);
                        g_A[(r0 + row) * LLv + col] = c[mr][nf][i] + eb1[col];
                    }
            zacc2(c);
        }
    }
#pragma unroll
    for (int mr = 0; mr < 2; mr++)
#pragma unroll
        for (int nf = 0; nf < 4; nf++)
#pragma unroll
            for (int i = 0; i < 4; i++) {
                int row = wm * 32 + mr * 16 + g + (i >> 1) * 8;
                int col = wn * 32 + nf * 8 + 2 * tig + (i & 1);
                g_Bv[(r0 + row) * LLv + col] = c[mr][nf][i];
            }
}

// ---------------- final mean over nodes (two-stage) ---------------------------
__global__ void mean1_kernel() {
    // grid (BB, 4), 512 threads; block sums 256 nodes -> g_part[b][seg][l]
    int b = blockIdx.x, seg = blockIdx.y, t = threadIdx.x;
    int l = t & 127, sub = t >> 7;           // 4 subs x 64 nodes
    const float* p = g_h + (b * NQv + seg * 256 + sub * 64) * LLv + l;
    float s = 0.f;
#pragma unroll 8
    for (int q = 0; q < 64; q++) s += p[q * LLv];
    __shared__ float red[4][LLv];
    red[sub][l] = s;
    __syncthreads();
    if (sub == 0)
        g_part[(b * 4 + seg) * LLv + l] =
            (red[0][l] + red[1][l]) + (red[2][l] + red[3][l]);
}

__global__ void mean2_kernel(float* __restrict__ out) {
    int b = blockIdx.x, l = threadIdx.x;     // 64 blocks x 128
    const float* p = g_part + b * 4 * LLv + l;
    out[b * LLv + l] =
        ((p[0] + p[LLv]) + (p[2 * LLv] + p[3 * LLv])) * (1.f / 1024.f);
}

// ---------------- launch ------------------------------------------------------
extern "C" void kernel_launch(void* const* d_in, const int* in_sizes, int n_in,
                              void* d_out, int out_size) {
    const float* z0    = (const float*)d_in[0];
    const void*  eidx  = d_in[1];
    const float* eattr = (const float*)d_in[2];
    const float* ew1 = (const float*)d_in[4];
    const float* eb1 = (const float*)d_in[5];
    const float* ew2 = (const float*)d_in[6];
    const float* eb2 = (const float*)d_in[7];
    const float* nw1 = (const float*)d_in[8];
    const float* nb1 = (const float*)d_in[9];
    const float* lng = (const float*)d_in[10];
    const float* lnb = (const float*)d_in[11];
    const float* nw2 = (const float*)d_in[12];
    const float* nb2 = (const float*)d_in[13];
    float* out = (float*)d_out;

    cudaFuncSetAttribute(round_kernel,
        cudaFuncAttributeMaxDynamicSharedMemorySize, RK_SMEM);
    cudaFuncSetAttribute(proj_kernel,
        cudaFuncAttributeMaxDynamicSharedMemorySize, PJ_SMEM);

    setup_kernel<<<1, 1024>>>(eidx, eb1);
    fill_kernel<<<NQv / 8, 256>>>(eattr);
    repack_kernel<<<705, 256>>>(ew1, ew2, nw1, nw2);

    round_kernel<<<dim3(NQv / 32, BB), 256, RK_SMEM>>>(   // launch index 3
        z0, eb2, nb1, lng, lnb, nb2, 0);

    proj_kernel<<<BB * NQv / 64, 256, PJ_SMEM>>>(eb1 + 128);
    round_kernel<<<dim3(NQv / 32, BB), 256, RK_SMEM>>>(
        z0, eb2 + LLv, nb1 + LLv,
        lng + LLv, lnb + LLv, nb2 + LLv, 1);

    mean1_kernel<<<dim3(BB, 4), 512>>>();
    mean2_kernel<<<BB, LLv>>>(out);
}